// round 1
// baseline (speedup 1.0000x reference)
#include <cuda_runtime.h>
#include <cuda_bf16.h>
#include <cstdint>

#define NSEQ  2048
#define HIDD  1024
#define NHEAD 16
#define HS    64
#define SAMPLED_ELEMS (16ULL * 2048ULL * 2048ULL)   // 67108864

// Scratch for Q and K projections (16 MB total). V goes straight to d_out tail.
__device__ float g_Q[NSEQ * HIDD];
__device__ float g_K[NSEQ * HIDD];

// ---------------- packed f32x2 helpers (FFMA2) ----------------
__device__ __forceinline__ unsigned long long pack2(float x, float y) {
    unsigned long long r;
    asm("mov.b64 %0, {%1, %2};" : "=l"(r) : "f"(x), "f"(y));
    return r;
}
__device__ __forceinline__ void unpack2(unsigned long long v, float &x, float &y) {
    asm("mov.b64 {%0, %1}, %2;" : "=f"(x), "=f"(y) : "l"(v));
}
__device__ __forceinline__ void ffma2(unsigned long long &d, unsigned long long a,
                                      unsigned long long b) {
    asm("fma.rn.f32x2 %0, %1, %2, %0;" : "+l"(d) : "l"(a), "l"(b));
}

// ---------------- GEMM: C[2048,1024] = A[2048,1024] @ W[1024,1024] + bias ----
// 64x64 tiles, BK=16, 256 threads, 4x4 per thread, packed f32x2 accumulation.
__global__ void __launch_bounds__(256) gemm_bias_kernel(
    const float* __restrict__ A, const float* __restrict__ W,
    const float* __restrict__ bias, float* __restrict__ C)
{
    __shared__ float As[16][64];   // [k][m]
    __shared__ float Bs[16][64];   // [k][n]

    const int tid = threadIdx.x;
    const int tx = tid & 15, ty = tid >> 4;
    const int row0 = blockIdx.y * 64, col0 = blockIdx.x * 64;

    // loader mapping
    const int ar = tid >> 2, ak = (tid & 3) << 2;   // A: 64 rows x 16 k
    const int wr = tid >> 4, wc = (tid & 15) << 2;  // W: 16 rows x 64 cols

    const float* Aptr = A + (size_t)(row0 + ar) * HIDD + ak;
    const float* Wptr = W + (size_t)wr * HIDD + col0 + wc;

    unsigned long long acc[4][2];
#pragma unroll
    for (int i = 0; i < 4; i++) { acc[i][0] = 0ULL; acc[i][1] = 0ULL; }

    for (int k0 = 0; k0 < HIDD; k0 += 16) {
        float4 a4 = *(const float4*)(Aptr + k0);
        As[ak + 0][ar] = a4.x;
        As[ak + 1][ar] = a4.y;
        As[ak + 2][ar] = a4.z;
        As[ak + 3][ar] = a4.w;
        *(float4*)&Bs[wr][wc] = *(const float4*)(Wptr + (size_t)k0 * HIDD);
        __syncthreads();

#pragma unroll
        for (int kk = 0; kk < 16; kk++) {
            float ra[4];
            *(float4*)ra = *(const float4*)&As[kk][ty * 4];
            unsigned long long rb0 = *(const unsigned long long*)&Bs[kk][tx * 4];
            unsigned long long rb1 = *(const unsigned long long*)&Bs[kk][tx * 4 + 2];
#pragma unroll
            for (int i = 0; i < 4; i++) {
                unsigned long long pa = pack2(ra[i], ra[i]);
                ffma2(acc[i][0], pa, rb0);
                ffma2(acc[i][1], pa, rb1);
            }
        }
        __syncthreads();
    }

    float4 b4 = *(const float4*)&bias[col0 + tx * 4];
#pragma unroll
    for (int i = 0; i < 4; i++) {
        float x0, x1, x2, x3;
        unpack2(acc[i][0], x0, x1);
        unpack2(acc[i][1], x2, x3);
        float4 o = make_float4(x0 + b4.x, x1 + b4.y, x2 + b4.z, x3 + b4.w);
        *(float4*)&C[(size_t)(row0 + ty * 4 + i) * HIDD + col0 + tx * 4] = o;
    }
}

// ---------------- Attention scores + argmax + one-hot write ----------------
// One block = (head h, 32 query rows). 256 threads = 8 warps x 4 q-rows.
// Keys tiled 128 at a time, K held transposed in smem as float2 pairs over d.
__global__ void __launch_bounds__(256) attn_argmax_kernel(
    const float* __restrict__ mask, float* __restrict__ out)
{
    const int h  = blockIdx.y;
    const int q0 = blockIdx.x * 32;

    const float* __restrict__ Qh = g_Q + (size_t)h * (NSEQ / NHEAD) * HIDD; // [2048][64]
    const float* __restrict__ Kh = g_K + (size_t)h * (NSEQ / NHEAD) * HIDD; // [2048][64]

    __shared__ unsigned long long Qs2[32][32];    // [q][dpair]      8 KB
    __shared__ unsigned long long Kt2[32][129];   // [dpair][key]   33 KB (padded)
    __shared__ int s_idx[32];

    const int tid = threadIdx.x;
    const int lane = tid & 31, warp = tid >> 5;
    const int qw0 = warp * 4;   // this warp's first local q row

    // load Q tile (32 rows x 64 d as 32 float2 each)
    for (int i = tid; i < 32 * 32; i += 256) {
        int q = i >> 5, dp = i & 31;
        Qs2[q][dp] = *(const unsigned long long*)&Qh[(size_t)(q0 + q) * HS + dp * 2];
    }

    float mval[4];
    int   midx[4];
#pragma unroll
    for (int i = 0; i < 4; i++) { mval[i] = -__int_as_float(0x7f800000); midx[i] = 0; }

    for (int kt = 0; kt < NSEQ; kt += 128) {
        __syncthreads();   // protect previous tile's reads (and first-iter Qs2 store order)
        // load 128 keys x 64 d, transposed into Kt2[dp][key]
        for (int i = tid; i < 128 * 32; i += 256) {
            int key = i >> 5, dp = i & 31;
            Kt2[dp][key] = *(const unsigned long long*)&Kh[(size_t)(kt + key) * HS + dp * 2];
        }
        __syncthreads();

        unsigned long long acc[4][4];   // [key-slot][q]
#pragma unroll
        for (int s = 0; s < 4; s++)
#pragma unroll
            for (int q = 0; q < 4; q++) acc[s][q] = 0ULL;

#pragma unroll
        for (int dc = 0; dc < 4; dc++) {
            unsigned long long qreg[4][8];
#pragma unroll
            for (int q = 0; q < 4; q++)
#pragma unroll
                for (int dp = 0; dp < 8; dp++)
                    qreg[q][dp] = Qs2[qw0 + q][dc * 8 + dp];
#pragma unroll
            for (int s = 0; s < 4; s++) {
                const int key = s * 32 + lane;
#pragma unroll
                for (int dp = 0; dp < 8; dp++) {
                    unsigned long long kv = Kt2[dc * 8 + dp][key];
                    ffma2(acc[s][0], kv, qreg[0][dp]);
                    ffma2(acc[s][1], kv, qreg[1][dp]);
                    ffma2(acc[s][2], kv, qreg[2][dp]);
                    ffma2(acc[s][3], kv, qreg[3][dp]);
                }
            }
        }

        // finalize: pair-sum, scale, mask, running argmax (first-index-wins)
#pragma unroll
        for (int s = 0; s < 4; s++) {
            const int key = kt + s * 32 + lane;
#pragma unroll
            for (int q = 0; q < 4; q++) {
                float x, y;
                unpack2(acc[s][q], x, y);
                float dot = x + y;
                float m = mask[(size_t)(q0 + qw0 + q) * NSEQ + key];
                float val = dot * 0.125f + (1.0f - m) * -10000.0f;
                if (val > mval[q]) { mval[q] = val; midx[q] = key; }
            }
        }
    }

    // cross-lane argmax reduction (ties -> smallest index, matching jnp.argmax)
#pragma unroll
    for (int q = 0; q < 4; q++) {
        float v = mval[q];
        int   ix = midx[q];
#pragma unroll
        for (int off = 16; off; off >>= 1) {
            float v2 = __shfl_xor_sync(0xffffffffu, v, off);
            int   i2 = __shfl_xor_sync(0xffffffffu, ix, off);
            if (v2 > v || (v2 == v && i2 < ix)) { v = v2; ix = i2; }
        }
        if (lane == 0) s_idx[qw0 + q] = ix;
    }
    __syncthreads();

    // write the 32 one-hot rows (zeros + single 1.0), fully covering d_out poison
    float* base = out + ((size_t)h * NSEQ + q0) * NSEQ;
    for (int q = 0; q < 32; q++) {
        const int am = s_idx[q];
        float4* rowp = (float4*)(base + (size_t)q * NSEQ);
#pragma unroll
        for (int i = tid; i < NSEQ / 4; i += 256) {
            float4 vv = make_float4(0.f, 0.f, 0.f, 0.f);
            if ((am >> 2) == i) ((float*)&vv)[am & 3] = 1.0f;
            rowp[i] = vv;
        }
    }
}

// ---------------- launch ----------------
extern "C" void kernel_launch(void* const* d_in, const int* in_sizes, int n_in,
                              void* d_out, int out_size)
{
    const float* q_in  = (const float*)d_in[0];
    const float* k_in  = (const float*)d_in[1];
    const float* v_in  = (const float*)d_in[2];
    const float* mask  = (const float*)d_in[3];
    const float* Wq    = (const float*)d_in[4];
    const float* bq    = (const float*)d_in[5];
    const float* Wk    = (const float*)d_in[6];
    const float* bk    = (const float*)d_in[7];
    const float* Wv    = (const float*)d_in[8];
    const float* bv    = (const float*)d_in[9];
    float* out = (float*)d_out;

    static float* gq = nullptr;
    static float* gk = nullptr;
    if (!gq) {
        cudaGetSymbolAddress((void**)&gq, g_Q);
        cudaGetSymbolAddress((void**)&gk, g_K);
    }

    dim3 ggrid(HIDD / 64, NSEQ / 64);   // 16 x 32
    gemm_bias_kernel<<<ggrid, 256>>>(q_in, Wq, bq, gq);
    gemm_bias_kernel<<<ggrid, 256>>>(k_in, Wk, bk, gk);
    gemm_bias_kernel<<<ggrid, 256>>>(v_in, Wv, bv, out + SAMPLED_ELEMS);

    dim3 agrid(NSEQ / 32, NHEAD);       // 64 x 16
    attn_argmax_kernel<<<agrid, 256>>>(mask, out);
}

// round 2
// speedup vs baseline: 1.3317x; 1.3317x over previous
#include <cuda_runtime.h>
#include <cuda_bf16.h>
#include <cstdint>

#define NSEQ  2048
#define HIDD  1024
#define NHEAD 16
#define HS    64
#define SAMPLED_ELEMS (16ULL * 2048ULL * 2048ULL)   // 67108864

typedef unsigned long long u64;

// Scratch for Q and K projections (16 MB total). V goes straight to d_out tail.
__device__ float g_Q[NSEQ * HIDD];
__device__ float g_K[NSEQ * HIDD];

// ---------------- packed f32x2 helpers (FFMA2) ----------------
__device__ __forceinline__ u64 pack2(float x, float y) {
    u64 r;
    asm("mov.b64 %0, {%1, %2};" : "=l"(r) : "f"(x), "f"(y));
    return r;
}
__device__ __forceinline__ void unpack2(u64 v, float &x, float &y) {
    asm("mov.b64 {%0, %1}, %2;" : "=f"(x), "=f"(y) : "l"(v));
}
__device__ __forceinline__ void ffma2(u64 &d, u64 a, u64 b) {
    asm("fma.rn.f32x2 %0, %1, %2, %0;" : "+l"(d) : "l"(a), "l"(b));
}

// =====================================================================
// Fused 3x GEMM: C[2048,1024] = A[2048,1024] @ W[1024,1024] + bias
// 128x128 tiles, BK=16 double-buffered, 256 thr, 8x8/thread,
// m-pair-packed f32x2 accumulators (A pairs come free from LDS.128).
// =====================================================================
__global__ void __launch_bounds__(256) gemm3_kernel(
    const float* __restrict__ Aq, const float* __restrict__ Ak, const float* __restrict__ Av,
    const float* __restrict__ Wq, const float* __restrict__ Wk, const float* __restrict__ Wv,
    const float* __restrict__ bq, const float* __restrict__ bk, const float* __restrict__ bv,
    float* __restrict__ Cq, float* __restrict__ Ck, float* __restrict__ Cv)
{
    __shared__ float As[2][16][132];   // [buf][k][m] (pad 132 keeps 16B align, spreads store banks)
    __shared__ float Bs[2][16][128];   // [buf][k][n]

    const int tid = threadIdx.x;
    const int mat = blockIdx.z;
    const float* A    = (mat == 0) ? Aq : (mat == 1) ? Ak : Av;
    const float* W    = (mat == 0) ? Wq : (mat == 1) ? Wk : Wv;
    const float* bias = (mat == 0) ? bq : (mat == 1) ? bk : bv;
    float*       C    = (mat == 0) ? Cq : (mat == 1) ? Ck : Cv;

    const int row0 = blockIdx.y * 128, col0 = blockIdx.x * 128;

    // loader mapping
    const int ar = tid >> 1;           // 0..127 (A row)
    const int ak = (tid & 1) * 8;      // 0 or 8 (A k-offset)
    const int wr = tid >> 4;           // 0..15  (W k-row)
    const int wc = (tid & 15) * 8;     // 0..120 (W col-offset)

    const float* Ap = A + (size_t)(row0 + ar) * HIDD + ak;
    const float* Wp = W + (size_t)wr * HIDD + col0 + wc;

    // compute mapping: thread (tx, ty); n-cols {4tx..4tx+3} and {64+4tx..+3}; m-rows ty*8..+7
    const int tx = tid & 15, ty = tid >> 4;

    // preload tile 0
    float4 a0 = *(const float4*)(Ap);
    float4 a1 = *(const float4*)(Ap + 4);
    float4 b0 = *(const float4*)(Wp);
    float4 b1 = *(const float4*)(Wp + 4);

    As[0][ak + 0][ar] = a0.x; As[0][ak + 1][ar] = a0.y;
    As[0][ak + 2][ar] = a0.z; As[0][ak + 3][ar] = a0.w;
    As[0][ak + 4][ar] = a1.x; As[0][ak + 5][ar] = a1.y;
    As[0][ak + 6][ar] = a1.z; As[0][ak + 7][ar] = a1.w;
    *(float4*)&Bs[0][wr][wc]     = b0;
    *(float4*)&Bs[0][wr][wc + 4] = b1;
    __syncthreads();

    u64 acc[4][8];   // [m-pair][n-frag]
#pragma unroll
    for (int i = 0; i < 4; i++)
#pragma unroll
        for (int j = 0; j < 8; j++) acc[i][j] = 0ULL;

    for (int t = 0; t < 64; t++) {
        const int buf = t & 1;
        if (t < 63) {   // prefetch next tile into registers (latency hidden by compute)
            const float* Ap2 = Ap + (t + 1) * 16;
            const float* Wp2 = Wp + (size_t)(t + 1) * 16 * HIDD;
            a0 = *(const float4*)(Ap2);
            a1 = *(const float4*)(Ap2 + 4);
            b0 = *(const float4*)(Wp2);
            b1 = *(const float4*)(Wp2 + 4);
        }
#pragma unroll
        for (int kk = 0; kk < 16; kk++) {
            ulonglong2 aa0 = *(const ulonglong2*)&As[buf][kk][ty * 8];
            ulonglong2 aa1 = *(const ulonglong2*)&As[buf][kk][ty * 8 + 4];
            float4 bv0 = *(const float4*)&Bs[buf][kk][4 * tx];
            float4 bv1 = *(const float4*)&Bs[buf][kk][64 + 4 * tx];
            u64 am[4] = {aa0.x, aa0.y, aa1.x, aa1.y};
            u64 bp[8] = {pack2(bv0.x, bv0.x), pack2(bv0.y, bv0.y),
                         pack2(bv0.z, bv0.z), pack2(bv0.w, bv0.w),
                         pack2(bv1.x, bv1.x), pack2(bv1.y, bv1.y),
                         pack2(bv1.z, bv1.z), pack2(bv1.w, bv1.w)};
#pragma unroll
            for (int mp = 0; mp < 4; mp++)
#pragma unroll
                for (int j = 0; j < 8; j++)
                    ffma2(acc[mp][j], am[mp], bp[j]);
        }
        if (t < 63) {
            const int nb = buf ^ 1;
            As[nb][ak + 0][ar] = a0.x; As[nb][ak + 1][ar] = a0.y;
            As[nb][ak + 2][ar] = a0.z; As[nb][ak + 3][ar] = a0.w;
            As[nb][ak + 4][ar] = a1.x; As[nb][ak + 5][ar] = a1.y;
            As[nb][ak + 6][ar] = a1.z; As[nb][ak + 7][ar] = a1.w;
            *(float4*)&Bs[nb][wr][wc]     = b0;
            *(float4*)&Bs[nb][wr][wc + 4] = b1;
            __syncthreads();
        }
    }

    // epilogue: + bias, store
    float4 bb0 = *(const float4*)&bias[col0 + 4 * tx];
    float4 bb1 = *(const float4*)&bias[col0 + 64 + 4 * tx];
#pragma unroll
    for (int p = 0; p < 8; p++) {
        const int row = row0 + ty * 8 + p;
        const int mp = p >> 1, hi = p & 1;
        float c[8];
#pragma unroll
        for (int j = 0; j < 8; j++) {
            float lo, hh;
            unpack2(acc[mp][j], lo, hh);
            c[j] = hi ? hh : lo;
        }
        float4 o0 = make_float4(c[0] + bb0.x, c[1] + bb0.y, c[2] + bb0.z, c[3] + bb0.w);
        float4 o1 = make_float4(c[4] + bb1.x, c[5] + bb1.y, c[6] + bb1.z, c[7] + bb1.w);
        *(float4*)&C[(size_t)row * HIDD + col0 + 4 * tx]      = o0;
        *(float4*)&C[(size_t)row * HIDD + col0 + 64 + 4 * tx] = o1;
    }
}

// =====================================================================
// Attention scores + argmax + interleaved zero-fill + one-hot scatter.
// Block = (head, 64 q rows), 128 threads, thread-tile 8q x 8keys.
// Smem holds Q and K transposed as [d-pair][idx] so q-frags broadcast
// and k-frags are contiguous LDS.128 (conflict-free).
// =====================================================================
__global__ void __launch_bounds__(128, 2) attn_argmax_kernel(
    const float* __restrict__ mask, float* __restrict__ out)
{
    __shared__ u64 Qs2[32][64];    // [dp][q]   16 KB
    __shared__ u64 Kt2[32][128];   // [dp][key] 32 KB

    const int h  = blockIdx.y;
    const int q0 = blockIdx.x * 64;
    const float* __restrict__ Qh = g_Q + (size_t)h * 131072;   // [2048][64]
    const float* __restrict__ Kh = g_K + (size_t)h * 131072;

    const int tid = threadIdx.x;
    const int tk = tid & 15;     // key group (16)
    const int tq = tid >> 4;     // q group (8)

    // load Q tile: 64 q x 64 d -> Qs2[dp][q]
    {
        const int q = tid >> 1, half = tid & 1;
        const float* src = Qh + (size_t)(q0 + q) * HS + half * 32;
#pragma unroll
        for (int c = 0; c < 8; c++) {
            float4 v = *(const float4*)(src + 4 * c);
            const int dp = half * 16 + 2 * c;
            Qs2[dp][q]     = pack2(v.x, v.y);
            Qs2[dp + 1][q] = pack2(v.z, v.w);
        }
    }

    float mval[8];
    int   midx[8];
#pragma unroll
    for (int i = 0; i < 8; i++) { mval[i] = -__int_as_float(0x7f800000); midx[i] = 0; }

    float* outbase = out + ((size_t)h * NSEQ + q0) * NSEQ;

    for (int kt = 0; kt < 16; kt++) {
        __syncthreads();   // previous tile fully consumed (also orders Q stores)
        {   // load 128 keys x 64 d -> Kt2[dp][key]
            const float* src = Kh + (size_t)(kt * 128 + tid) * HS;
#pragma unroll
            for (int c = 0; c < 16; c++) {
                float4 v = *(const float4*)(src + 4 * c);
                Kt2[2 * c][tid]     = pack2(v.x, v.y);
                Kt2[2 * c + 1][tid] = pack2(v.z, v.w);
            }
        }
        __syncthreads();

        u64 acc[8][8];   // [q][i4*2+s], pair-over-d
#pragma unroll
        for (int q = 0; q < 8; q++)
#pragma unroll
            for (int j = 0; j < 8; j++) acc[q][j] = 0ULL;

#pragma unroll 8
        for (int dp = 0; dp < 32; dp++) {
            ulonglong2 q01 = *(const ulonglong2*)&Qs2[dp][tq * 8];
            ulonglong2 q23 = *(const ulonglong2*)&Qs2[dp][tq * 8 + 2];
            ulonglong2 q45 = *(const ulonglong2*)&Qs2[dp][tq * 8 + 4];
            ulonglong2 q67 = *(const ulonglong2*)&Qs2[dp][tq * 8 + 6];
            u64 qf[8] = {q01.x, q01.y, q23.x, q23.y, q45.x, q45.y, q67.x, q67.y};
            ulonglong2 k0 = *(const ulonglong2*)&Kt2[dp][2 * tk];
            ulonglong2 k1 = *(const ulonglong2*)&Kt2[dp][32 + 2 * tk];
            ulonglong2 k2 = *(const ulonglong2*)&Kt2[dp][64 + 2 * tk];
            ulonglong2 k3 = *(const ulonglong2*)&Kt2[dp][96 + 2 * tk];
            u64 kf[8] = {k0.x, k0.y, k1.x, k1.y, k2.x, k2.y, k3.x, k3.y};
#pragma unroll
            for (int q = 0; q < 8; q++)
#pragma unroll
                for (int j = 0; j < 8; j++)
                    ffma2(acc[q][j], qf[q], kf[j]);
        }

        // finalize: pair-sum, scale, mask, running argmax (first-index-wins)
#pragma unroll
        for (int q = 0; q < 8; q++) {
            const size_t mrow = (size_t)(q0 + tq * 8 + q) * NSEQ;
#pragma unroll
            for (int i4 = 0; i4 < 4; i4++) {
                const int keyl = i4 * 32 + 2 * tk;
                const int key  = kt * 128 + keyl;
                float2 m2 = *(const float2*)&mask[mrow + key];
                float x, y;
                unpack2(acc[q][2 * i4], x, y);
                float v0 = (x + y) * 0.125f + (1.0f - m2.x) * -10000.0f;
                unpack2(acc[q][2 * i4 + 1], x, y);
                float v1 = (x + y) * 0.125f + (1.0f - m2.y) * -10000.0f;
                if (v0 > mval[q]) { mval[q] = v0; midx[q] = key; }
                if (v1 > mval[q]) { mval[q] = v1; midx[q] = key + 1; }
            }
        }

        // interleaved zero-fill: 4 rows of this block's output per tile
        {
            const int r  = kt * 4 + (tid >> 5);
            const int c0 = tid & 31;
            float4* rowp = (float4*)(outbase + (size_t)r * NSEQ);
            const float4 z = make_float4(0.f, 0.f, 0.f, 0.f);
#pragma unroll
            for (int j = 0; j < 16; j++) rowp[c0 + 32 * j] = z;
        }
    }

    // cross-lane argmax reduction within each 16-lane tk group
    __syncthreads();
    int* s_idx = (int*)&Qs2[0][0];
#pragma unroll
    for (int q = 0; q < 8; q++) {
        float v = mval[q];
        int   ix = midx[q];
#pragma unroll
        for (int off = 8; off; off >>= 1) {
            float v2 = __shfl_xor_sync(0xffffffffu, v, off, 16);
            int   i2 = __shfl_xor_sync(0xffffffffu, ix, off, 16);
            if (v2 > v || (v2 == v && i2 < ix)) { v = v2; ix = i2; }
        }
        if (tk == 0) s_idx[tq * 8 + q] = ix;
    }
    __syncthreads();

    // scatter the 64 ones (rows already zero-filled)
    if (tid < 64) {
        const int am = s_idx[tid];
        outbase[(size_t)tid * NSEQ + am] = 1.0f;
    }
}

// ---------------- launch ----------------
extern "C" void kernel_launch(void* const* d_in, const int* in_sizes, int n_in,
                              void* d_out, int out_size)
{
    const float* q_in = (const float*)d_in[0];
    const float* k_in = (const float*)d_in[1];
    const float* v_in = (const float*)d_in[2];
    const float* mask = (const float*)d_in[3];
    const float* Wq   = (const float*)d_in[4];
    const float* bq   = (const float*)d_in[5];
    const float* Wk   = (const float*)d_in[6];
    const float* bk   = (const float*)d_in[7];
    const float* Wv   = (const float*)d_in[8];
    const float* bv   = (const float*)d_in[9];
    float* out = (float*)d_out;

    static float* gq = nullptr;
    static float* gk = nullptr;
    if (!gq) {
        cudaGetSymbolAddress((void**)&gq, g_Q);
        cudaGetSymbolAddress((void**)&gk, g_K);
    }

    dim3 ggrid(HIDD / 128, NSEQ / 128, 3);   // 8 x 16 x 3 = 384 blocks
    gemm3_kernel<<<ggrid, 256>>>(q_in, k_in, v_in, Wq, Wk, Wv, bq, bk, bv,
                                 gq, gk, out + SAMPLED_ELEMS);

    dim3 agrid(NSEQ / 64, NHEAD);            // 32 x 16 = 512 blocks
    attn_argmax_kernel<<<agrid, 128>>>(mask, out);
}

// round 3
// speedup vs baseline: 1.3317x; 1.0001x over previous
#include <cuda_runtime.h>
#include <cuda_bf16.h>
#include <cstdint>

#define NSEQ  2048
#define HIDD  1024
#define NHEAD 16
#define HS    64
#define SAMPLED_ELEMS (16ULL * 2048ULL * 2048ULL)   // 67108864

typedef unsigned long long u64;

// Scratch for Q and K projections (16 MB total). V goes straight to d_out tail.
__device__ float g_Q[NSEQ * HIDD];
__device__ float g_K[NSEQ * HIDD];

// ---------------- packed f32x2 helpers (FFMA2) ----------------
__device__ __forceinline__ u64 pack2(float x, float y) {
    u64 r;
    asm("mov.b64 %0, {%1, %2};" : "=l"(r) : "f"(x), "f"(y));
    return r;
}
__device__ __forceinline__ void unpack2(u64 v, float &x, float &y) {
    asm("mov.b64 {%0, %1}, %2;" : "=f"(x), "=f"(y) : "l"(v));
}
__device__ __forceinline__ void ffma2(u64 &d, u64 a, u64 b) {
    asm("fma.rn.f32x2 %0, %1, %2, %0;" : "+l"(d) : "l"(a), "l"(b));
}

// =====================================================================
// Fused 3x GEMM: C[2048,1024] = A[2048,1024] @ W[1024,1024] + bias
// 128x128 tiles, BK=16 double-buffered, 256 thr, 8x8/thread,
// m-pair-packed f32x2 accumulators (A pairs come free from LDS.128).
// =====================================================================
__global__ void __launch_bounds__(256) gemm3_kernel(
    const float* __restrict__ Aq, const float* __restrict__ Ak, const float* __restrict__ Av,
    const float* __restrict__ Wq, const float* __restrict__ Wk, const float* __restrict__ Wv,
    const float* __restrict__ bq, const float* __restrict__ bk, const float* __restrict__ bv,
    float* __restrict__ Cq, float* __restrict__ Ck, float* __restrict__ Cv)
{
    __shared__ float As[2][16][132];   // [buf][k][m] (pad 132 keeps 16B align, spreads store banks)
    __shared__ float Bs[2][16][128];   // [buf][k][n]

    const int tid = threadIdx.x;
    const int mat = blockIdx.z;
    const float* A    = (mat == 0) ? Aq : (mat == 1) ? Ak : Av;
    const float* W    = (mat == 0) ? Wq : (mat == 1) ? Wk : Wv;
    const float* bias = (mat == 0) ? bq : (mat == 1) ? bk : bv;
    float*       C    = (mat == 0) ? Cq : (mat == 1) ? Ck : Cv;

    const int row0 = blockIdx.y * 128, col0 = blockIdx.x * 128;

    // loader mapping
    const int ar = tid >> 1;           // 0..127 (A row)
    const int ak = (tid & 1) * 8;      // 0 or 8 (A k-offset)
    const int wr = tid >> 4;           // 0..15  (W k-row)
    const int wc = (tid & 15) * 8;     // 0..120 (W col-offset)

    const float* Ap = A + (size_t)(row0 + ar) * HIDD + ak;
    const float* Wp = W + (size_t)wr * HIDD + col0 + wc;

    // compute mapping: thread (tx, ty); n-cols {4tx..4tx+3} and {64+4tx..+3}; m-rows ty*8..+7
    const int tx = tid & 15, ty = tid >> 4;

    // preload tile 0
    float4 a0 = *(const float4*)(Ap);
    float4 a1 = *(const float4*)(Ap + 4);
    float4 b0 = *(const float4*)(Wp);
    float4 b1 = *(const float4*)(Wp + 4);

    As[0][ak + 0][ar] = a0.x; As[0][ak + 1][ar] = a0.y;
    As[0][ak + 2][ar] = a0.z; As[0][ak + 3][ar] = a0.w;
    As[0][ak + 4][ar] = a1.x; As[0][ak + 5][ar] = a1.y;
    As[0][ak + 6][ar] = a1.z; As[0][ak + 7][ar] = a1.w;
    *(float4*)&Bs[0][wr][wc]     = b0;
    *(float4*)&Bs[0][wr][wc + 4] = b1;
    __syncthreads();

    u64 acc[4][8];   // [m-pair][n-frag]
#pragma unroll
    for (int i = 0; i < 4; i++)
#pragma unroll
        for (int j = 0; j < 8; j++) acc[i][j] = 0ULL;

    for (int t = 0; t < 64; t++) {
        const int buf = t & 1;
        if (t < 63) {   // prefetch next tile into registers (latency hidden by compute)
            const float* Ap2 = Ap + (t + 1) * 16;
            const float* Wp2 = Wp + (size_t)(t + 1) * 16 * HIDD;
            a0 = *(const float4*)(Ap2);
            a1 = *(const float4*)(Ap2 + 4);
            b0 = *(const float4*)(Wp2);
            b1 = *(const float4*)(Wp2 + 4);
        }
#pragma unroll
        for (int kk = 0; kk < 16; kk++) {
            ulonglong2 aa0 = *(const ulonglong2*)&As[buf][kk][ty * 8];
            ulonglong2 aa1 = *(const ulonglong2*)&As[buf][kk][ty * 8 + 4];
            float4 bv0 = *(const float4*)&Bs[buf][kk][4 * tx];
            float4 bv1 = *(const float4*)&Bs[buf][kk][64 + 4 * tx];
            u64 am[4] = {aa0.x, aa0.y, aa1.x, aa1.y};
            u64 bp[8] = {pack2(bv0.x, bv0.x), pack2(bv0.y, bv0.y),
                         pack2(bv0.z, bv0.z), pack2(bv0.w, bv0.w),
                         pack2(bv1.x, bv1.x), pack2(bv1.y, bv1.y),
                         pack2(bv1.z, bv1.z), pack2(bv1.w, bv1.w)};
#pragma unroll
            for (int mp = 0; mp < 4; mp++)
#pragma unroll
                for (int j = 0; j < 8; j++)
                    ffma2(acc[mp][j], am[mp], bp[j]);
        }
        if (t < 63) {
            const int nb = buf ^ 1;
            As[nb][ak + 0][ar] = a0.x; As[nb][ak + 1][ar] = a0.y;
            As[nb][ak + 2][ar] = a0.z; As[nb][ak + 3][ar] = a0.w;
            As[nb][ak + 4][ar] = a1.x; As[nb][ak + 5][ar] = a1.y;
            As[nb][ak + 6][ar] = a1.z; As[nb][ak + 7][ar] = a1.w;
            *(float4*)&Bs[nb][wr][wc]     = b0;
            *(float4*)&Bs[nb][wr][wc + 4] = b1;
            __syncthreads();
        }
    }

    // epilogue: + bias, store
    float4 bb0 = *(const float4*)&bias[col0 + 4 * tx];
    float4 bb1 = *(const float4*)&bias[col0 + 64 + 4 * tx];
#pragma unroll
    for (int p = 0; p < 8; p++) {
        const int row = row0 + ty * 8 + p;
        const int mp = p >> 1, hi = p & 1;
        float c[8];
#pragma unroll
        for (int j = 0; j < 8; j++) {
            float lo, hh;
            unpack2(acc[mp][j], lo, hh);
            c[j] = hi ? hh : lo;
        }
        float4 o0 = make_float4(c[0] + bb0.x, c[1] + bb0.y, c[2] + bb0.z, c[3] + bb0.w);
        float4 o1 = make_float4(c[4] + bb1.x, c[5] + bb1.y, c[6] + bb1.z, c[7] + bb1.w);
        *(float4*)&C[(size_t)row * HIDD + col0 + 4 * tx]      = o0;
        *(float4*)&C[(size_t)row * HIDD + col0 + 64 + 4 * tx] = o1;
    }
}

// =====================================================================
// Attention scores + argmax + interleaved zero-fill + one-hot scatter.
// Block = (head, 64 q rows), 128 threads, thread-tile 8q x 8keys.
// Smem holds Q and K transposed as [d-pair][idx] so q-frags broadcast
// and k-frags are contiguous LDS.128 (conflict-free).
// =====================================================================
__global__ void __launch_bounds__(128, 2) attn_argmax_kernel(
    const float* __restrict__ mask, float* __restrict__ out)
{
    __shared__ u64 Qs2[32][64];    // [dp][q]   16 KB
    __shared__ u64 Kt2[32][128];   // [dp][key] 32 KB

    const int h  = blockIdx.y;
    const int q0 = blockIdx.x * 64;
    const float* __restrict__ Qh = g_Q + (size_t)h * 131072;   // [2048][64]
    const float* __restrict__ Kh = g_K + (size_t)h * 131072;

    const int tid = threadIdx.x;
    const int tk = tid & 15;     // key group (16)
    const int tq = tid >> 4;     // q group (8)

    // load Q tile: 64 q x 64 d -> Qs2[dp][q]
    {
        const int q = tid >> 1, half = tid & 1;
        const float* src = Qh + (size_t)(q0 + q) * HS + half * 32;
#pragma unroll
        for (int c = 0; c < 8; c++) {
            float4 v = *(const float4*)(src + 4 * c);
            const int dp = half * 16 + 2 * c;
            Qs2[dp][q]     = pack2(v.x, v.y);
            Qs2[dp + 1][q] = pack2(v.z, v.w);
        }
    }

    float mval[8];
    int   midx[8];
#pragma unroll
    for (int i = 0; i < 8; i++) { mval[i] = -__int_as_float(0x7f800000); midx[i] = 0; }

    float* outbase = out + ((size_t)h * NSEQ + q0) * NSEQ;

    for (int kt = 0; kt < 16; kt++) {
        __syncthreads();   // previous tile fully consumed (also orders Q stores)
        {   // load 128 keys x 64 d -> Kt2[dp][key]
            const float* src = Kh + (size_t)(kt * 128 + tid) * HS;
#pragma unroll
            for (int c = 0; c < 16; c++) {
                float4 v = *(const float4*)(src + 4 * c);
                Kt2[2 * c][tid]     = pack2(v.x, v.y);
                Kt2[2 * c + 1][tid] = pack2(v.z, v.w);
            }
        }
        __syncthreads();

        u64 acc[8][8];   // [q][i4*2+s], pair-over-d
#pragma unroll
        for (int q = 0; q < 8; q++)
#pragma unroll
            for (int j = 0; j < 8; j++) acc[q][j] = 0ULL;

#pragma unroll 8
        for (int dp = 0; dp < 32; dp++) {
            ulonglong2 q01 = *(const ulonglong2*)&Qs2[dp][tq * 8];
            ulonglong2 q23 = *(const ulonglong2*)&Qs2[dp][tq * 8 + 2];
            ulonglong2 q45 = *(const ulonglong2*)&Qs2[dp][tq * 8 + 4];
            ulonglong2 q67 = *(const ulonglong2*)&Qs2[dp][tq * 8 + 6];
            u64 qf[8] = {q01.x, q01.y, q23.x, q23.y, q45.x, q45.y, q67.x, q67.y};
            ulonglong2 k0 = *(const ulonglong2*)&Kt2[dp][2 * tk];
            ulonglong2 k1 = *(const ulonglong2*)&Kt2[dp][32 + 2 * tk];
            ulonglong2 k2 = *(const ulonglong2*)&Kt2[dp][64 + 2 * tk];
            ulonglong2 k3 = *(const ulonglong2*)&Kt2[dp][96 + 2 * tk];
            u64 kf[8] = {k0.x, k0.y, k1.x, k1.y, k2.x, k2.y, k3.x, k3.y};
#pragma unroll
            for (int q = 0; q < 8; q++)
#pragma unroll
                for (int j = 0; j < 8; j++)
                    ffma2(acc[q][j], qf[q], kf[j]);
        }

        // finalize: pair-sum, scale, mask, running argmax (first-index-wins)
#pragma unroll
        for (int q = 0; q < 8; q++) {
            const size_t mrow = (size_t)(q0 + tq * 8 + q) * NSEQ;
#pragma unroll
            for (int i4 = 0; i4 < 4; i4++) {
                const int keyl = i4 * 32 + 2 * tk;
                const int key  = kt * 128 + keyl;
                float2 m2 = *(const float2*)&mask[mrow + key];
                float x, y;
                unpack2(acc[q][2 * i4], x, y);
                float v0 = (x + y) * 0.125f + (1.0f - m2.x) * -10000.0f;
                unpack2(acc[q][2 * i4 + 1], x, y);
                float v1 = (x + y) * 0.125f + (1.0f - m2.y) * -10000.0f;
                if (v0 > mval[q]) { mval[q] = v0; midx[q] = key; }
                if (v1 > mval[q]) { mval[q] = v1; midx[q] = key + 1; }
            }
        }

        // interleaved zero-fill: 4 rows of this block's output per tile
        {
            const int r  = kt * 4 + (tid >> 5);
            const int c0 = tid & 31;
            float4* rowp = (float4*)(outbase + (size_t)r * NSEQ);
            const float4 z = make_float4(0.f, 0.f, 0.f, 0.f);
#pragma unroll
            for (int j = 0; j < 16; j++) rowp[c0 + 32 * j] = z;
        }
    }

    // cross-lane argmax reduction within each 16-lane tk group
    __syncthreads();
    int* s_idx = (int*)&Qs2[0][0];
#pragma unroll
    for (int q = 0; q < 8; q++) {
        float v = mval[q];
        int   ix = midx[q];
#pragma unroll
        for (int off = 8; off; off >>= 1) {
            float v2 = __shfl_xor_sync(0xffffffffu, v, off, 16);
            int   i2 = __shfl_xor_sync(0xffffffffu, ix, off, 16);
            if (v2 > v || (v2 == v && i2 < ix)) { v = v2; ix = i2; }
        }
        if (tk == 0) s_idx[tq * 8 + q] = ix;
    }
    __syncthreads();

    // scatter the 64 ones (rows already zero-filled)
    if (tid < 64) {
        const int am = s_idx[tid];
        outbase[(size_t)tid * NSEQ + am] = 1.0f;
    }
}

// ---------------- launch ----------------
extern "C" void kernel_launch(void* const* d_in, const int* in_sizes, int n_in,
                              void* d_out, int out_size)
{
    const float* q_in = (const float*)d_in[0];
    const float* k_in = (const float*)d_in[1];
    const float* v_in = (const float*)d_in[2];
    const float* mask = (const float*)d_in[3];
    const float* Wq   = (const float*)d_in[4];
    const float* bq   = (const float*)d_in[5];
    const float* Wk   = (const float*)d_in[6];
    const float* bk   = (const float*)d_in[7];
    const float* Wv   = (const float*)d_in[8];
    const float* bv   = (const float*)d_in[9];
    float* out = (float*)d_out;

    static float* gq = nullptr;
    static float* gk = nullptr;
    if (!gq) {
        cudaGetSymbolAddress((void**)&gq, g_Q);
        cudaGetSymbolAddress((void**)&gk, g_K);
    }

    dim3 ggrid(HIDD / 128, NSEQ / 128, 3);   // 8 x 16 x 3 = 384 blocks
    gemm3_kernel<<<ggrid, 256>>>(q_in, k_in, v_in, Wq, Wk, Wv, bq, bk, bv,
                                 gq, gk, out + SAMPLED_ELEMS);

    dim3 agrid(NSEQ / 64, NHEAD);            // 32 x 16 = 512 blocks
    attn_argmax_kernel<<<agrid, 128>>>(mask, out);
}